// round 9
// baseline (speedup 1.0000x reference)
#include <cuda_runtime.h>
#include <cstdint>

// FlowNetC correlation cost volume. Inputs [B=8, C=128, H=128, W=256] fp32.
// out[b, (dy+4)*9+(dx+4), y, x] = (1/128) * sum_c in1[b,c,y,x] * in2z[b,c,y+dy,x+dx]
//
// R8: dy-PAIR blocking. Block = (dy-group, y-tile of 8 rows, b*2+xhalf).
// Groups 0..3 handle dy = {2g-4, 2g-3}; group 4 handles dy = 4 alone.
// Each warp owns one output row and a 128-col half, keeps 72 accumulators
// (2 dy x 9 dx x 4 x), and stages TWO in2 rows (gy0, gy0+1) per channel into
// warp-private double-buffered smem via cp.async (CHUNK=4 channels/phase).
// One in1 LDG.128 per channel now feeds both dy -> L2 'a' traffic halves.
// Even-dx uses packed fma.rn.f32x2; odd-dx scalar. No block barriers.

#define B_     8
#define C_     128
#define H_     128
#define W_     256
#define CHUNK  4                    // channels per staged chunk
#define ROWF   136                  // floats per row window (4-col halo each side)
#define PHASEF (CHUNK * 2 * ROWF)   // 1088 floats per phase (2 rows per channel)
#define WARPBUF (2 * PHASEF)        // 2176 floats per warp (double buffer)
#define SMEM_BYTES (8 * WARPBUF * 4)  // 69,632 B per block -> 2 CTAs/SM

__device__ __forceinline__ void cp_async16(void* dst_smem, const void* src_gmem) {
    uint32_t d = (uint32_t)__cvta_generic_to_shared(dst_smem);
    asm volatile("cp.async.cg.shared.global [%0], [%1], 16;"
                 :: "r"(d), "l"(src_gmem) : "memory");
}
__device__ __forceinline__ void cp_commit() {
    asm volatile("cp.async.commit_group;" ::: "memory");
}
template <int N>
__device__ __forceinline__ void cp_wait() {
    asm volatile("cp.async.wait_group %0;" :: "n"(N) : "memory");
}
__device__ __forceinline__ unsigned long long pk2(float lo, float hi) {
    unsigned long long r;
    asm("mov.b64 %0, {%1, %2};" : "=l"(r) : "f"(lo), "f"(hi));
    return r;
}
__device__ __forceinline__ void fma2(unsigned long long& d,
                                     unsigned long long a, unsigned long long b) {
    asm("fma.rn.f32x2 %0, %1, %2, %0;" : "+l"(d) : "l"(a), "l"(b));
}
__device__ __forceinline__ float2 up2(unsigned long long v) {
    float2 r;
    asm("mov.b64 {%0, %1}, %2;" : "=f"(r.x), "=f"(r.y) : "l"(v));
    return r;
}

extern __shared__ float s_mem[];

__global__ __launch_bounds__(256, 2)
void corr_kernel(const float* __restrict__ in1,
                 const float* __restrict__ in2,
                 float* __restrict__ out)
{
    const int g     = (int)blockIdx.x;            // 0..4 dy-group
    const int dy0   = (g < 4) ? (2 * g - 4) : 4;  // first dy of group
    const bool two  = (g < 4);                    // group has a second dy?
    const int y0    = (int)blockIdx.y * 8;
    const int b     = (int)blockIdx.z >> 1;
    const int xh    = (int)blockIdx.z & 1;        // 128-col half
    const int xbase = xh << 7;
    const int w     = (int)threadIdx.x >> 5;      // warp id = row in tile
    const int lane  = (int)threadIdx.x & 31;
    const int y     = y0 + w;
    const int gy0   = y + dy0;
    const int gy1   = gy0 + 1;
    const bool ok0  = (unsigned)gy0 < (unsigned)H_;
    const bool ok1  = two && ((unsigned)gy1 < (unsigned)H_);

    const float* in1b = in1 + (size_t)b * C_ * H_ * W_;
    const float* r0g  = in2 + (size_t)b * C_ * H_ * W_ + (size_t)(ok0 ? gy0 : 0) * W_;
    const float* r1g  = in2 + (size_t)b * C_ * H_ * W_ + (size_t)(ok1 ? gy1 : 0) * W_;

    float* wbuf = s_mem + w * WARPBUF;

    // Zero warp-private buffer once: halos and OOB/absent rows stay zero.
    for (int i = lane; i < WARPBUF; i += 32) wbuf[i] = 0.0f;
    __syncwarp();

    // accumulators: [dy][...]  even dx packed (5 x 2 ull), odd dx scalar (4 x 4)
    unsigned long long acc2[2][5][2];
    float acco[2][4][4];
#pragma unroll
    for (int t = 0; t < 2; ++t) {
#pragma unroll
        for (int e = 0; e < 5; ++e) { acc2[t][e][0] = 0ull; acc2[t][e][1] = 0ull; }
#pragma unroll
        for (int e = 0; e < 4; ++e)
#pragma unroll
            for (int i = 0; i < 4; ++i) acco[t][e][i] = 0.0f;
    }

    // Stage CHUNK channels x 2 rows into phase ph.
    // Row slots: float4 slot s <-> global f4 index g0+s, valid iff 0<=g0+s<64.
    const int g0 = (xh << 5) - 1;
    auto stage = [&](int c0, int ph) {
        float* pb = wbuf + ph * PHASEF;
#pragma unroll
        for (int c = 0; c < CHUNK; ++c) {
            const size_t coff = (size_t)(c0 + c) * H_ * W_;
            float* d0 = pb + (c * 2 + 0) * ROWF;
            float* d1 = pb + (c * 2 + 1) * ROWF;
            int gf4 = g0 + lane;                  // slots 0..31
            bool inb = (unsigned)gf4 < 64u;
            if (ok0 && inb) cp_async16(d0 + (lane << 2), r0g + coff + (gf4 << 2));
            if (ok1 && inb) cp_async16(d1 + (lane << 2), r1g + coff + (gf4 << 2));
            if (lane < 2) {                       // slots 32..33
                int gf4b = g0 + 32 + lane;
                bool inb2 = (unsigned)gf4b < 64u;
                if (ok0 && inb2) cp_async16(d0 + ((32 + lane) << 2), r0g + coff + (gf4b << 2));
                if (ok1 && inb2) cp_async16(d1 + ((32 + lane) << 2), r1g + coff + (gf4b << 2));
            }
        }
    };

    stage(0, 0);
    cp_commit();

    const int NCHUNK = C_ / CHUNK;   // 32
#pragma unroll 2
    for (int k = 0; k < NCHUNK; ++k) {
        if (k < NCHUNK - 1) {
            stage((k + 1) * CHUNK, (k + 1) & 1);
            cp_commit();
            cp_wait<1>();            // chunk k's group complete
        } else {
            cp_wait<0>();
        }
        __syncwarp();

        const float* pb   = wbuf + (k & 1) * PHASEF;
        const float* aptr = in1b + ((size_t)(k * CHUNK) * H_ + y) * W_
                                 + xbase + (lane << 2);

#pragma unroll
        for (int c = 0; c < CHUNK; ++c) {
            float4 a = *reinterpret_cast<const float4*>(aptr + (size_t)c * H_ * W_);
            unsigned long long a2lo = pk2(a.x, a.y);
            unsigned long long a2hi = pk2(a.z, a.w);
            float aa[4] = {a.x, a.y, a.z, a.w};

            // dy0 window (row 0 of this channel)
            {
                const float* br = pb + (c * 2 + 0) * ROWF + (lane << 2);
                float4 b0 = *reinterpret_cast<const float4*>(br);
                float4 b1 = *reinterpret_cast<const float4*>(br + 4);
                float4 b2 = *reinterpret_cast<const float4*>(br + 8);
                float bb[12] = {b0.x, b0.y, b0.z, b0.w,
                                b1.x, b1.y, b1.z, b1.w,
                                b2.x, b2.y, b2.z, b2.w};
                unsigned long long bp[6];
#pragma unroll
                for (int q = 0; q < 6; ++q) bp[q] = pk2(bb[2 * q], bb[2 * q + 1]);
#pragma unroll
                for (int e = 0; e < 5; ++e) {
                    fma2(acc2[0][e][0], a2lo, bp[e]);
                    fma2(acc2[0][e][1], a2hi, bp[e + 1]);
                }
#pragma unroll
                for (int e = 0; e < 4; ++e)
#pragma unroll
                    for (int i = 0; i < 4; ++i)
                        acco[0][e][i] = fmaf(aa[i], bb[i + 2 * e + 1], acco[0][e][i]);
            }
            // dy1 window (row 1) -- uniform branch, skipped for group 4
            if (two) {
                const float* br = pb + (c * 2 + 1) * ROWF + (lane << 2);
                float4 b0 = *reinterpret_cast<const float4*>(br);
                float4 b1 = *reinterpret_cast<const float4*>(br + 4);
                float4 b2 = *reinterpret_cast<const float4*>(br + 8);
                float bb[12] = {b0.x, b0.y, b0.z, b0.w,
                                b1.x, b1.y, b1.z, b1.w,
                                b2.x, b2.y, b2.z, b2.w};
                unsigned long long bp[6];
#pragma unroll
                for (int q = 0; q < 6; ++q) bp[q] = pk2(bb[2 * q], bb[2 * q + 1]);
#pragma unroll
                for (int e = 0; e < 5; ++e) {
                    fma2(acc2[1][e][0], a2lo, bp[e]);
                    fma2(acc2[1][e][1], a2hi, bp[e + 1]);
                }
#pragma unroll
                for (int e = 0; e < 4; ++e)
#pragma unroll
                    for (int i = 0; i < 4; ++i)
                        acco[1][e][i] = fmaf(aa[i], bb[i + 2 * e + 1], acco[1][e][i]);
            }
        }
        // no trailing barrier: LDS of chunk k completes ~29cyc after issue; the
        // earliest overwrite (chunk k+2's cp.async) lands >=234cyc later.
    }

    // ---- epilogue: scale by 1/C, one float4 store per (dy,dx) ----
    const float sc = 1.0f / (float)C_;
    const int ndy = two ? 2 : 1;
    for (int t = 0; t < ndy; ++t) {
        size_t ob = (((size_t)b * 81 + (size_t)(dy0 + t + 4) * 9) * H_ + y) * W_
                  + xbase + (lane << 2);
#pragma unroll
        for (int e = 0; e < 5; ++e) {             // d = 2e
            float2 lo = up2(acc2[t][e][0]), hi = up2(acc2[t][e][1]);
            float4 v = make_float4(lo.x * sc, lo.y * sc, hi.x * sc, hi.y * sc);
            *reinterpret_cast<float4*>(out + ob + (size_t)(2 * e) * H_ * W_) = v;
        }
#pragma unroll
        for (int e = 0; e < 4; ++e) {             // d = 2e+1
            float4 v = make_float4(acco[t][e][0] * sc, acco[t][e][1] * sc,
                                   acco[t][e][2] * sc, acco[t][e][3] * sc);
            *reinterpret_cast<float4*>(out + ob + (size_t)(2 * e + 1) * H_ * W_) = v;
        }
    }
}

extern "C" void kernel_launch(void* const* d_in, const int* in_sizes, int n_in,
                              void* d_out, int out_size)
{
    const float* in1 = (const float*)d_in[0];
    const float* in2 = (const float*)d_in[1];
    float* out = (float*)d_out;

    cudaFuncSetAttribute(corr_kernel,
                         cudaFuncAttributeMaxDynamicSharedMemorySize, SMEM_BYTES);

    // (dy-group, y-tile, b*2+xhalf); group fastest -> L2 reuse of shared rows
    dim3 grid(5, H_ / 8, B_ * 2);
    corr_kernel<<<grid, 256, SMEM_BYTES>>>(in1, in2, out);
}

// round 10
// speedup vs baseline: 1.5900x; 1.5900x over previous
#include <cuda_runtime.h>
#include <cstdint>

// FlowNetC correlation cost volume. Inputs [B=8, C=128, H=128, W=256] fp32.
// out[b, (dy+4)*9+(dx+4), y, x] = (1/128) * sum_c in1[b,c,y,x] * in2z[b,c,y+dy,x+dx]
//
// R9: dy-PAIR blocking at 1 CTA/SM (255-reg budget -> no accumulator spills).
// Block = (dy-group, y-tile of 8 rows, b*2+xhalf). Groups 0..3: dy={2g-4,2g-3};
// group 4: dy=4 alone. Warp = one output row, 128-col half, 72 accumulators
// (2 dy x 9 dx x 4 x). Two in2 rows per channel staged into warp-private
// double-buffered smem (CHUNK=8 channels/phase, 139KB total). One in1 LDG.128
// per channel feeds both dy -> L2 'a' traffic halves vs one-dy-per-block.
// Even dx packed fma.rn.f32x2; odd dx scalar. No block barriers.

#define B_     8
#define C_     128
#define H_     128
#define W_     256
#define CHUNK  8                    // channels per staged chunk
#define ROWF   136                  // floats per row window (4-col halo each side)
#define PHASEF (CHUNK * 2 * ROWF)   // 2176 floats per phase (2 rows per channel)
#define WARPBUF (2 * PHASEF)        // 4352 floats per warp (double buffer)
#define SMEM_BYTES (8 * WARPBUF * 4)  // 139,264 B per block -> 1 CTA/SM

__device__ __forceinline__ void cp_async16(void* dst_smem, const void* src_gmem) {
    uint32_t d = (uint32_t)__cvta_generic_to_shared(dst_smem);
    asm volatile("cp.async.cg.shared.global [%0], [%1], 16;"
                 :: "r"(d), "l"(src_gmem) : "memory");
}
__device__ __forceinline__ void cp_commit() {
    asm volatile("cp.async.commit_group;" ::: "memory");
}
template <int N>
__device__ __forceinline__ void cp_wait() {
    asm volatile("cp.async.wait_group %0;" :: "n"(N) : "memory");
}
__device__ __forceinline__ unsigned long long pk2(float lo, float hi) {
    unsigned long long r;
    asm("mov.b64 %0, {%1, %2};" : "=l"(r) : "f"(lo), "f"(hi));
    return r;
}
__device__ __forceinline__ void fma2(unsigned long long& d,
                                     unsigned long long a, unsigned long long b) {
    asm("fma.rn.f32x2 %0, %1, %2, %0;" : "+l"(d) : "l"(a), "l"(b));
}
__device__ __forceinline__ float2 up2(unsigned long long v) {
    float2 r;
    asm("mov.b64 {%0, %1}, %2;" : "=f"(r.x), "=f"(r.y) : "l"(v));
    return r;
}

extern __shared__ float s_mem[];

__global__ __launch_bounds__(256, 1)
void corr_kernel(const float* __restrict__ in1,
                 const float* __restrict__ in2,
                 float* __restrict__ out)
{
    const int g     = (int)blockIdx.x;            // 0..4 dy-group
    const int dy0   = (g < 4) ? (2 * g - 4) : 4;  // first dy of group
    const bool two  = (g < 4);                    // group has a second dy?
    const int y0    = (int)blockIdx.y * 8;
    const int b     = (int)blockIdx.z >> 1;
    const int xh    = (int)blockIdx.z & 1;        // 128-col half
    const int xbase = xh << 7;
    const int w     = (int)threadIdx.x >> 5;      // warp id = row in tile
    const int lane  = (int)threadIdx.x & 31;
    const int y     = y0 + w;
    const int gy0   = y + dy0;
    const int gy1   = gy0 + 1;
    const bool ok0  = (unsigned)gy0 < (unsigned)H_;
    const bool ok1  = two && ((unsigned)gy1 < (unsigned)H_);

    const float* in1b = in1 + (size_t)b * C_ * H_ * W_;
    const float* r0g  = in2 + (size_t)b * C_ * H_ * W_ + (size_t)(ok0 ? gy0 : 0) * W_;
    const float* r1g  = in2 + (size_t)b * C_ * H_ * W_ + (size_t)(ok1 ? gy1 : 0) * W_;

    float* wbuf = s_mem + w * WARPBUF;

    // Zero warp-private buffer once: halos and OOB/absent rows stay zero.
    for (int i = lane; i < WARPBUF; i += 32) wbuf[i] = 0.0f;
    __syncwarp();

    // accumulators: [dy][...]  even dx packed (5 x 2 ull), odd dx scalar (4 x 4)
    unsigned long long acc2[2][5][2];
    float acco[2][4][4];
#pragma unroll
    for (int t = 0; t < 2; ++t) {
#pragma unroll
        for (int e = 0; e < 5; ++e) { acc2[t][e][0] = 0ull; acc2[t][e][1] = 0ull; }
#pragma unroll
        for (int e = 0; e < 4; ++e)
#pragma unroll
            for (int i = 0; i < 4; ++i) acco[t][e][i] = 0.0f;
    }

    // Stage CHUNK channels x 2 rows into phase ph.
    // Row slots: float4 slot s <-> global f4 index g0+s, valid iff 0<=g0+s<64.
    const int g0 = (xh << 5) - 1;
    auto stage = [&](int c0, int ph) {
        float* pb = wbuf + ph * PHASEF;
#pragma unroll
        for (int c = 0; c < CHUNK; ++c) {
            const size_t coff = (size_t)(c0 + c) * H_ * W_;
            float* d0 = pb + (c * 2 + 0) * ROWF;
            float* d1 = pb + (c * 2 + 1) * ROWF;
            int gf4 = g0 + lane;                  // slots 0..31
            bool inb = (unsigned)gf4 < 64u;
            if (ok0 && inb) cp_async16(d0 + (lane << 2), r0g + coff + (gf4 << 2));
            if (ok1 && inb) cp_async16(d1 + (lane << 2), r1g + coff + (gf4 << 2));
            if (lane < 2) {                       // slots 32..33
                int gf4b = g0 + 32 + lane;
                bool inb2 = (unsigned)gf4b < 64u;
                if (ok0 && inb2) cp_async16(d0 + ((32 + lane) << 2), r0g + coff + (gf4b << 2));
                if (ok1 && inb2) cp_async16(d1 + ((32 + lane) << 2), r1g + coff + (gf4b << 2));
            }
        }
    };

    stage(0, 0);
    cp_commit();

    const int NCHUNK = C_ / CHUNK;   // 16
#pragma unroll 2
    for (int k = 0; k < NCHUNK; ++k) {
        if (k < NCHUNK - 1) {
            stage((k + 1) * CHUNK, (k + 1) & 1);
            cp_commit();
            cp_wait<1>();            // chunk k's group complete
        } else {
            cp_wait<0>();
        }
        __syncwarp();

        const float* pb   = wbuf + (k & 1) * PHASEF;
        const float* aptr = in1b + ((size_t)(k * CHUNK) * H_ + y) * W_
                                 + xbase + (lane << 2);

#pragma unroll
        for (int c = 0; c < CHUNK; ++c) {
            float4 a = *reinterpret_cast<const float4*>(aptr + (size_t)c * H_ * W_);
            unsigned long long a2lo = pk2(a.x, a.y);
            unsigned long long a2hi = pk2(a.z, a.w);
            float aa[4] = {a.x, a.y, a.z, a.w};

            // dy0 window (row 0 of this channel)
            {
                const float* br = pb + (c * 2 + 0) * ROWF + (lane << 2);
                float4 b0 = *reinterpret_cast<const float4*>(br);
                float4 b1 = *reinterpret_cast<const float4*>(br + 4);
                float4 b2 = *reinterpret_cast<const float4*>(br + 8);
                float bb[12] = {b0.x, b0.y, b0.z, b0.w,
                                b1.x, b1.y, b1.z, b1.w,
                                b2.x, b2.y, b2.z, b2.w};
                unsigned long long bp[6];
#pragma unroll
                for (int q = 0; q < 6; ++q) bp[q] = pk2(bb[2 * q], bb[2 * q + 1]);
#pragma unroll
                for (int e = 0; e < 5; ++e) {
                    fma2(acc2[0][e][0], a2lo, bp[e]);
                    fma2(acc2[0][e][1], a2hi, bp[e + 1]);
                }
#pragma unroll
                for (int e = 0; e < 4; ++e)
#pragma unroll
                    for (int i = 0; i < 4; ++i)
                        acco[0][e][i] = fmaf(aa[i], bb[i + 2 * e + 1], acco[0][e][i]);
            }
            // dy1 window (row 1) -- uniform branch, skipped for group 4
            if (two) {
                const float* br = pb + (c * 2 + 1) * ROWF + (lane << 2);
                float4 b0 = *reinterpret_cast<const float4*>(br);
                float4 b1 = *reinterpret_cast<const float4*>(br + 4);
                float4 b2 = *reinterpret_cast<const float4*>(br + 8);
                float bb[12] = {b0.x, b0.y, b0.z, b0.w,
                                b1.x, b1.y, b1.z, b1.w,
                                b2.x, b2.y, b2.z, b2.w};
                unsigned long long bp[6];
#pragma unroll
                for (int q = 0; q < 6; ++q) bp[q] = pk2(bb[2 * q], bb[2 * q + 1]);
#pragma unroll
                for (int e = 0; e < 5; ++e) {
                    fma2(acc2[1][e][0], a2lo, bp[e]);
                    fma2(acc2[1][e][1], a2hi, bp[e + 1]);
                }
#pragma unroll
                for (int e = 0; e < 4; ++e)
#pragma unroll
                    for (int i = 0; i < 4; ++i)
                        acco[1][e][i] = fmaf(aa[i], bb[i + 2 * e + 1], acco[1][e][i]);
            }
        }
        // no trailing barrier: LDS of chunk k completes ~29cyc after issue; the
        // earliest overwrite (chunk k+2's cp.async) lands >=234cyc later.
    }

    // ---- epilogue: scale by 1/C, one float4 store per (dy,dx) ----
    const float sc = 1.0f / (float)C_;
    const int ndy = two ? 2 : 1;
    for (int t = 0; t < ndy; ++t) {
        size_t ob = (((size_t)b * 81 + (size_t)(dy0 + t + 4) * 9) * H_ + y) * W_
                  + xbase + (lane << 2);
#pragma unroll
        for (int e = 0; e < 5; ++e) {             // d = 2e
            float2 lo = up2(acc2[t][e][0]), hi = up2(acc2[t][e][1]);
            float4 v = make_float4(lo.x * sc, lo.y * sc, hi.x * sc, hi.y * sc);
            *reinterpret_cast<float4*>(out + ob + (size_t)(2 * e) * H_ * W_) = v;
        }
#pragma unroll
        for (int e = 0; e < 4; ++e) {             // d = 2e+1
            float4 v = make_float4(acco[t][e][0] * sc, acco[t][e][1] * sc,
                                   acco[t][e][2] * sc, acco[t][e][3] * sc);
            *reinterpret_cast<float4*>(out + ob + (size_t)(2 * e + 1) * H_ * W_) = v;
        }
    }
}

extern "C" void kernel_launch(void* const* d_in, const int* in_sizes, int n_in,
                              void* d_out, int out_size)
{
    const float* in1 = (const float*)d_in[0];
    const float* in2 = (const float*)d_in[1];
    float* out = (float*)d_out;

    cudaFuncSetAttribute(corr_kernel,
                         cudaFuncAttributeMaxDynamicSharedMemorySize, SMEM_BYTES);

    // (dy-group, y-tile, b*2+xhalf); group fastest -> L2 reuse of shared rows
    dim3 grid(5, H_ / 8, B_ * 2);
    corr_kernel<<<grid, 256, SMEM_BYTES>>>(in1, in2, out);
}

// round 11
// speedup vs baseline: 1.8549x; 1.1666x over previous
#include <cuda_runtime.h>
#include <cstdint>

// FlowNetC correlation cost volume. Inputs [B=8, C=128, H=128, W=256] fp32.
// out[b, (dy+4)*9+(dx+4), y, x] = (1/128) * sum_c in1[b,c,y,x] * in2z[b,c,y+dy,x+dx]
//
// R10: full-row warps, two-quad x ownership, fully packed f32x2.
// Block = 4 warps (128 thr); warp w owns output row y0+w for ONE dy, covering
// all 256 cols as two quads: cols 4*lane and 128+4*lane (16B lane stride ->
// conflict-free LDS.128). 72 accumulators/thread as 36 f32x2 regs.
// Warp-autonomous cp.async staging of the full 264-float in2 row window
// (4-col zero halos), double-buffered, CHUNK=8 channels/phase. 3 CTAs/SM
// (launch_bounds(128,3) -> 168-reg cap), 12 warps/SM. No block barriers.

#define B_     8
#define C_     128
#define H_     128
#define W_     256
#define CHUNK  8                     // channels per staged phase
#define ROWF   264                   // floats per row window (cols -4..259)
#define PHASEF (CHUNK * ROWF)        // 2112 floats
#define WARPBUF (2 * PHASEF)         // 4224 floats (double buffer)
#define SMEM_BYTES (4 * WARPBUF * 4) // 67,584 B per CTA -> 3 CTAs/SM

__device__ __forceinline__ void cp_async16(void* dst_smem, const void* src_gmem) {
    uint32_t d = (uint32_t)__cvta_generic_to_shared(dst_smem);
    asm volatile("cp.async.cg.shared.global [%0], [%1], 16;"
                 :: "r"(d), "l"(src_gmem) : "memory");
}
__device__ __forceinline__ void cp_commit() {
    asm volatile("cp.async.commit_group;" ::: "memory");
}
template <int N>
__device__ __forceinline__ void cp_wait() {
    asm volatile("cp.async.wait_group %0;" :: "n"(N) : "memory");
}
__device__ __forceinline__ unsigned long long pk2(float lo, float hi) {
    unsigned long long r;
    asm("mov.b64 %0, {%1, %2};" : "=l"(r) : "f"(lo), "f"(hi));
    return r;
}
__device__ __forceinline__ void fma2(unsigned long long& d,
                                     unsigned long long a, unsigned long long b) {
    asm("fma.rn.f32x2 %0, %1, %2, %0;" : "+l"(d) : "l"(a), "l"(b));
}
__device__ __forceinline__ float2 up2(unsigned long long v) {
    float2 r;
    asm("mov.b64 {%0, %1}, %2;" : "=f"(r.x), "=f"(r.y) : "l"(v));
    return r;
}

extern __shared__ float s_mem[];

__global__ __launch_bounds__(128, 3)
void corr_kernel(const float* __restrict__ in1,
                 const float* __restrict__ in2,
                 float* __restrict__ out)
{
    const int dy   = (int)blockIdx.x - 4;       // -4..4
    const int y0   = (int)blockIdx.y * 4;       // 4 rows per block (1 per warp)
    const int b    = (int)blockIdx.z;
    const int w    = (int)threadIdx.x >> 5;     // warp id = row in tile
    const int lane = (int)threadIdx.x & 31;
    const int y    = y0 + w;
    const int gy   = y + dy;
    const bool rowok = (unsigned)gy < (unsigned)H_;

    const float* in1b = in1 + (size_t)b * C_ * H_ * W_;
    const float* in2g = in2 + (size_t)b * C_ * H_ * W_ + (size_t)(rowok ? gy : 0) * W_;

    float* wbuf = s_mem + w * WARPBUF;

    // Zero once: halo floats (0..3, 260..263 of each row) and OOB rows stay 0.
    for (int i = lane; i < WARPBUF; i += 32) wbuf[i] = 0.0f;
    __syncwarp();

    // Accumulators: [quad][...] even dx (e=0..4) and odd dx (e=0..3), each as
    // f32x2 pairs over p=0..1 (output cols xq+2p, xq+2p+1). 36 ull = 72 regs.
    unsigned long long ae[2][5][2], ao[2][4][2];
#pragma unroll
    for (int q = 0; q < 2; ++q) {
#pragma unroll
        for (int e = 0; e < 5; ++e) { ae[q][e][0] = 0ull; ae[q][e][1] = 0ull; }
#pragma unroll
        for (int e = 0; e < 4; ++e) { ao[q][e][0] = 0ull; ao[q][e][1] = 0ull; }
    }

    // Stage CHUNK channels of the full row window into phase ph.
    // Buffer float j <-> global col j-4. Valid float4 slots s=1..64 map to
    // global f4 index s-1; lane covers s=1+lane and s=33+lane (both valid).
    auto stage = [&](int c0, int ph) {
        if (!rowok) return;
        float* pb = wbuf + ph * PHASEF;
#pragma unroll
        for (int c = 0; c < CHUNK; ++c) {
            const float* src = in2g + (size_t)(c0 + c) * H_ * W_;
            float* drow = pb + c * ROWF;
            cp_async16(drow + 4 * (1 + lane),  src + 4 * lane);
            cp_async16(drow + 4 * (33 + lane), src + 4 * (32 + lane));
        }
    };

    stage(0, 0);
    cp_commit();

    const int NCHUNK = C_ / CHUNK;   // 16
#pragma unroll 2
    for (int k = 0; k < NCHUNK; ++k) {
        if (k < NCHUNK - 1) {
            stage((k + 1) * CHUNK, (k + 1) & 1);
            cp_commit();
            cp_wait<1>();            // chunk k's group complete
        } else {
            cp_wait<0>();
        }
        __syncwarp();

        const float* pb    = wbuf + (k & 1) * PHASEF;
        const float* abase = in1b + ((size_t)(k * CHUNK) * H_ + y) * W_;

#pragma unroll
        for (int c = 0; c < CHUNK; ++c) {
            const float* arow = abase + (size_t)c * H_ * W_;
            const float* brow = pb + c * ROWF;

#pragma unroll
            for (int q = 0; q < 2; ++q) {
                const int xq = (q << 7) + (lane << 2);          // 4*lane or 128+4*lane
                float4 a = *reinterpret_cast<const float4*>(arow + xq);
                // window: buffer floats xq .. xq+11  <->  cols xq-4 .. xq+7
                const float* br = brow + xq;
                float4 b0 = *reinterpret_cast<const float4*>(br);
                float4 b1 = *reinterpret_cast<const float4*>(br + 4);
                float4 b2 = *reinterpret_cast<const float4*>(br + 8);
                float bb[12] = {b0.x, b0.y, b0.z, b0.w,
                                b1.x, b1.y, b1.z, b1.w,
                                b2.x, b2.y, b2.z, b2.w};

                unsigned long long ap[2] = {pk2(a.x, a.y), pk2(a.z, a.w)};
                unsigned long long bp[6], bo[5];
#pragma unroll
                for (int i = 0; i < 6; ++i) bp[i] = pk2(bb[2 * i], bb[2 * i + 1]); // aligned: free
#pragma unroll
                for (int i = 0; i < 5; ++i) bo[i] = pk2(bb[2 * i + 1], bb[2 * i + 2]); // packs

                // even d = 2e: acc += (a[2p],a[2p+1]) * (bb[2(p+e)], bb[2(p+e)+1])
#pragma unroll
                for (int e = 0; e < 5; ++e) {
                    fma2(ae[q][e][0], ap[0], bp[e]);
                    fma2(ae[q][e][1], ap[1], bp[e + 1]);
                }
                // odd d = 2e+1: acc += (a[2p],a[2p+1]) * (bb[2(p+e)+1], bb[2(p+e)+2])
#pragma unroll
                for (int e = 0; e < 4; ++e) {
                    fma2(ao[q][e][0], ap[0], bo[e]);
                    fma2(ao[q][e][1], ap[1], bo[e + 1]);
                }
            }
        }
        // no barrier: LDS of chunk k done ~29cyc after issue; earliest
        // overwrite (chunk k+2's cp.async) lands >=234cyc after its issue.
    }

    // ---- epilogue: scale by 1/C, two float4 stores (quads) per dx ----
    const float sc = 1.0f / (float)C_;
    const size_t obrow = (((size_t)b * 81 + (size_t)(dy + 4) * 9) * H_ + y) * W_;
#pragma unroll
    for (int q = 0; q < 2; ++q) {
        const int xq = (q << 7) + (lane << 2);
#pragma unroll
        for (int e = 0; e < 5; ++e) {             // d = 2e
            float2 lo = up2(ae[q][e][0]), hi = up2(ae[q][e][1]);
            float4 v = make_float4(lo.x * sc, lo.y * sc, hi.x * sc, hi.y * sc);
            *reinterpret_cast<float4*>(out + obrow + (size_t)(2 * e) * H_ * W_ + xq) = v;
        }
#pragma unroll
        for (int e = 0; e < 4; ++e) {             // d = 2e+1
            float2 lo = up2(ao[q][e][0]), hi = up2(ao[q][e][1]);
            float4 v = make_float4(lo.x * sc, lo.y * sc, hi.x * sc, hi.y * sc);
            *reinterpret_cast<float4*>(out + obrow + (size_t)(2 * e + 1) * H_ * W_ + xq) = v;
        }
    }
}

extern "C" void kernel_launch(void* const* d_in, const int* in_sizes, int n_in,
                              void* d_out, int out_size)
{
    const float* in1 = (const float*)d_in[0];
    const float* in2 = (const float*)d_in[1];
    float* out = (float*)d_out;

    cudaFuncSetAttribute(corr_kernel,
                         cudaFuncAttributeMaxDynamicSharedMemorySize, SMEM_BYTES);

    // (dy, y-tile of 4 rows, batch); dy fastest -> L2 reuse of a/b rows
    dim3 grid(9, H_ / 4, B_);
    corr_kernel<<<grid, 128, SMEM_BYTES>>>(in1, in2, out);
}